// round 6
// baseline (speedup 1.0000x reference)
#include <cuda_runtime.h>
#include <cstdint>

// Problem constants: B=4, H=64, W=2048, C=128, N=1e6
#define GB 4
#define GH 64
#define GW 2048
#define CELLS (GB * GH * GW)       // 524288 total
#define PCELLS (GH * GW)           // 131072 cells per batch-slice
#define NC 128
#define NMAX (1 << 20)             // >= 1e6 points

// Per-pass scratch: one batch-slice of sums, fp32 = 64 MB (L2-resident).
__device__ __align__(256) float g_sums[(size_t)PCELLS * NC];
// Full-grid counts (2 MB) + precomputed flat cell index per point (4 MB).
__device__ float g_cnt[CELLS];
__device__ int   g_cell[NMAX];

__global__ void zero_cnt_kernel() {
    int i = blockIdx.x * blockDim.x + threadIdx.x;
    int stride = gridDim.x * blockDim.x;
    for (int k = i; k < CELLS; k += stride) g_cnt[k] = 0.f;
}

// Compute flat cell index per point + full-grid counts (atomics into 2 MB, L2).
__global__ void prep_kernel(const int* __restrict__ cb,
                            const int* __restrict__ cy,
                            const int* __restrict__ cx,
                            int N) {
    int i = blockIdx.x * blockDim.x + threadIdx.x;
    if (i >= N) return;
    int cell = (cb[i] * GH + cy[i]) * GW + cx[i];
    g_cell[i] = cell;
    atomicAdd(&g_cnt[cell], 1.0f);
}

__global__ void zero_sums_kernel() {
    long n4 = ((long)PCELLS * NC) / 4;   // 4M float4
    long i = (long)blockIdx.x * blockDim.x + threadIdx.x;
    long stride = (long)gridDim.x * blockDim.x;
    float4 z = make_float4(0.f, 0.f, 0.f, 0.f);
    float4* s4 = reinterpret_cast<float4*>(g_sums);
    for (long k = i; k < n4; k += stride) s4[k] = z;
}

// Warp = one point (32 lanes x float4 = 128 channels). Batch predicate is
// warp-uniform -> non-selected warps retire after one hot 4B load.
__global__ void scatter_kernel(const float* __restrict__ feat,
                               int N, int bsel) {
    long gid = (long)blockIdx.x * blockDim.x + threadIdx.x;
    int p  = (int)(gid >> 5);
    int ln = (int)(gid & 31);
    if (p >= N) return;

    int cell = g_cell[p];
    if ((cell >> 17) != bsel) return;        // PCELLS = 2^17
    int local = cell & (PCELLS - 1);

    // Stream feat past L2 (evict-first) to protect sums residency.
    float4 v = __ldcs(reinterpret_cast<const float4*>(feat) + (long)p * (NC / 4) + ln);

    float* dst = g_sums + (long)local * NC + ln * 4;
    asm volatile("red.global.add.v4.f32 [%0], {%1, %2, %3, %4};"
                 :: "l"(dst), "f"(v.x), "f"(v.y), "f"(v.z), "f"(v.w)
                 : "memory");
}

__global__ void gather_kernel(float* __restrict__ out,
                              int N, int bsel) {
    long gid = (long)blockIdx.x * blockDim.x + threadIdx.x;
    int p  = (int)(gid >> 5);
    int ln = (int)(gid & 31);
    if (p >= N) return;

    int cell = g_cell[p];
    if ((cell >> 17) != bsel) return;
    int local = cell & (PCELLS - 1);

    float cnt = __ldg(&g_cnt[cell]);         // warp-uniform broadcast
    float scale = 1.0f / fmaxf(cnt, 1.0f);

    float4 s = reinterpret_cast<const float4*>(g_sums)[(long)local * (NC / 4) + ln];
    float4 o = make_float4(s.x * scale, s.y * scale, s.z * scale, s.w * scale);

    // Stream output writes past L2.
    __stcs(reinterpret_cast<float4*>(out) + (long)p * (NC / 4) + ln, o);
}

extern "C" void kernel_launch(void* const* d_in, const int* in_sizes, int n_in,
                              void* d_out, int out_size) {
    const float* feat = (const float*)d_in[0];
    const int*   cb   = (const int*)d_in[1];
    const int*   cy   = (const int*)d_in[2];
    const int*   cx   = (const int*)d_in[3];
    float*       out  = (float*)d_out;

    int N = in_sizes[1];

    zero_cnt_kernel<<<512, 256>>>();
    prep_kernel<<<(N + 255) / 256, 256>>>(cb, cy, cx, N);

    long total = (long)N * 32;               // warp per point
    int blocks = (int)((total + 255) / 256);

    for (int b = 0; b < GB; b++) {
        zero_sums_kernel<<<2048, 256>>>();
        scatter_kernel<<<blocks, 256>>>(feat, N, b);
        gather_kernel<<<blocks, 256>>>(out, N, b);
    }
}

// round 8
// speedup vs baseline: 3.0106x; 3.0106x over previous
#include <cuda_runtime.h>
#include <cstdint>

// Problem constants: B=4, H=64, W=2048, C=128, N=1e6
#define GB 4
#define GH 64
#define GW 2048
#define CELLS (GB * GH * GW)       // 524288
#define NC 128
#define NMAX (1 << 20)             // >= 1e6 points

// Small index scratch only (no big sums array): ~16 MB total, L2-hot.
__device__ int g_cnt[CELLS];       // points per cell
__device__ int g_off[CELLS];       // base offset of each cell's group
__device__ int g_cur[CELLS];       // running cursor for counting sort
__device__ int g_cell[NMAX];       // flat cell id per point
__device__ int g_sorted[NMAX];     // point ids grouped by cell
__device__ int g_total;            // allocation counter

__global__ void zero_kernel() {
    int i = blockIdx.x * blockDim.x + threadIdx.x;
    int stride = gridDim.x * blockDim.x;
    for (int k = i; k < CELLS; k += stride) g_cnt[k] = 0;
    if (i == 0) g_total = 0;
}

__global__ void prep_kernel(const int* __restrict__ cb,
                            const int* __restrict__ cy,
                            const int* __restrict__ cx,
                            int N) {
    int i = blockIdx.x * blockDim.x + threadIdx.x;
    if (i >= N) return;
    int cell = (cb[i] * GH + cy[i]) * GW + cx[i];
    g_cell[i] = cell;
    atomicAdd(&g_cnt[cell], 1);
}

// Assign each cell a disjoint range [off, off+cnt). Order is irrelevant, so a
// warp-aggregated atomicAdd on one counter replaces a full prefix scan.
__global__ void alloc_kernel() {
    int i = blockIdx.x * blockDim.x + threadIdx.x;
    if (i >= CELLS) return;
    int ln = threadIdx.x & 31;
    int c = g_cnt[i];

    int incl = c;
    #pragma unroll
    for (int d = 1; d < 32; d <<= 1) {
        int t = __shfl_up_sync(0xFFFFFFFFu, incl, d);
        if (ln >= d) incl += t;
    }
    int wsum = __shfl_sync(0xFFFFFFFFu, incl, 31);
    int base = 0;
    if (ln == 31) base = atomicAdd(&g_total, wsum);
    base = __shfl_sync(0xFFFFFFFFu, base, 31);

    int off = base + incl - c;
    g_off[i] = off;
    g_cur[i] = off;
}

__global__ void sort_kernel(int N) {
    int i = blockIdx.x * blockDim.x + threadIdx.x;
    if (i >= N) return;
    int cell = g_cell[i];
    int pos = atomicAdd(&g_cur[cell], 1);
    g_sorted[pos] = i;
}

// Warp = one cell. Accumulate its points' rows in registers, write the mean
// to every member point's output row. float4/lane covers NC=128.
__global__ void mean_kernel(const float* __restrict__ feat,
                            float* __restrict__ out) {
    long gid = (long)blockIdx.x * blockDim.x + threadIdx.x;
    int cell = (int)(gid >> 5);
    int ln   = (int)(gid & 31);
    if (cell >= CELLS) return;

    int cnt = g_cnt[cell];
    if (cnt == 0) return;
    int off = g_off[cell];

    const float4* f4 = reinterpret_cast<const float4*>(feat);
    float4 acc = make_float4(0.f, 0.f, 0.f, 0.f);
    for (int j = 0; j < cnt; j++) {
        int id = g_sorted[off + j];                 // broadcast (L2-hot)
        float4 v = __ldcs(f4 + (long)id * (NC / 4) + ln);
        acc.x += v.x; acc.y += v.y; acc.z += v.z; acc.w += v.w;
    }
    float inv = 1.0f / (float)cnt;
    float4 m = make_float4(acc.x * inv, acc.y * inv, acc.z * inv, acc.w * inv);

    float4* o4 = reinterpret_cast<float4*>(out);
    for (int j = 0; j < cnt; j++) {
        int id = g_sorted[off + j];
        __stcs(o4 + (long)id * (NC / 4) + ln, m);
    }
}

extern "C" void kernel_launch(void* const* d_in, const int* in_sizes, int n_in,
                              void* d_out, int out_size) {
    const float* feat = (const float*)d_in[0];
    const int*   cb   = (const int*)d_in[1];
    const int*   cy   = (const int*)d_in[2];
    const int*   cx   = (const int*)d_in[3];
    float*       out  = (float*)d_out;

    int N = in_sizes[1];

    zero_kernel<<<512, 256>>>();
    prep_kernel<<<(N + 255) / 256, 256>>>(cb, cy, cx, N);
    alloc_kernel<<<CELLS / 256, 256>>>();
    sort_kernel<<<(N + 255) / 256, 256>>>(N);

    long mt = (long)CELLS * 32;
    mean_kernel<<<(int)((mt + 255) / 256), 256>>>(feat, out);
}